// round 11
// baseline (speedup 1.0000x reference)
#include <cuda_runtime.h>
#include <math.h>
#include <stdint.h>

#define B_   32
#define T_   512
#define E_   256
#define H_   512
#define L_   50
#define NT   256
#define NBLK 128     // recurrent blocks, 1/SM
#define NBG  64      // blocks per batch-group

typedef unsigned long long ull;

// ---------------- device globals -----------------------------------------------
__device__ __align__(16) float g_hT[2 * 2 * H_ * 16];   // [grp][buf][hd][16b]
__device__ __align__(16) float g_Y[T_ * H_ * B_];       // [t][hd][32b] (zero-init .bss)
__device__ __align__(16) float g_Zx[(size_t)T_ * 2048 * B_]; // [t][col][32b]
__device__ float g_acc[B_];
__device__ unsigned g_barc[2 * 32];                     // per-group counters, 128B apart

// ---------------- helpers --------------------------------------------------------
__device__ __forceinline__ ull ffma2_(ull a, ull b, ull c) {
    ull d;
    asm("fma.rn.f32x2 %0, %1, %2, %3;" : "=l"(d) : "l"(a), "l"(b), "l"(c));
    return d;
}
__device__ __forceinline__ ull splat2_(float x) {
    ull r; unsigned xi = __float_as_uint(x);
    asm("mov.b64 %0, {%1, %1};" : "=l"(r) : "r"(xi));
    return r;
}
__device__ __forceinline__ void cp16(uint32_t dst, const void* src) {
    asm volatile("cp.async.cg.shared.global [%0], [%1], 16;" :: "r"(dst), "l"(src));
}
__device__ __forceinline__ void cp_commit() { asm volatile("cp.async.commit_group;"); }
#define CP_WAIT(N) asm volatile("cp.async.wait_group %0;" :: "n"(N) : "memory")

__device__ __forceinline__ float fsig_(float x) {
    x = fminf(fmaxf(x, -30.f), 30.f);
    float e = __expf(-x);
    return __fdividef(1.f, 1.f + e);
}
__device__ __forceinline__ float ftanh_(float x) {
    x = fminf(fmaxf(x, -15.f), 15.f);
    float e = __expf(-2.f * x);
    return __fdividef(1.f - e, 1.f + e);
}

// ================================================================================
// Phase A: zx precompute.  grid = (T_ * 4); block 0 also resets state.
// Blocks with t >= max(lengths) exit early (outputs never consumed).
// ================================================================================
#define ZXD_OFF  0
#define ZWB_OFF  (256*32)
#define ZX_SMEM  ((8192 + 3*8192) * 4)
#define XT_PAD   261

__global__ void __launch_bounds__(256, 1)
zx_kernel(const int* __restrict__ q, const float* __restrict__ we,
          const float* __restrict__ W, const float* __restrict__ bvec,
          const int* __restrict__ lengths)
{
    extern __shared__ float sm[];
    float* XD = sm + ZXD_OFF;
    float* WB = sm + ZWB_OFF;
    float* XT = sm + ZWB_OFF;
    const uint32_t smu = (uint32_t)__cvta_generic_to_shared(sm);
    __shared__ int qrow[32];
    __shared__ int smax[1];

    const int tid = threadIdx.x;
    const int t   = blockIdx.x >> 2;
    const int c0  = (blockIdx.x & 3) << 9;

    if (blockIdx.x == 0) {                  // graph-replay-safe reset
        if (tid < 64) g_barc[tid] = 0u;
        if (tid < 32) g_acc[tid] = 0.f;
        float4 z4 = make_float4(0.f, 0.f, 0.f, 0.f);
        float4* hp4 = (float4*)g_hT;
        #pragma unroll
        for (int i = 0; i < 32; ++i) hp4[tid + (i << 8)] = z4;   // 32768 floats
    }

    if (tid < 32) {
        int v = lengths[tid];
        #pragma unroll
        for (int o = 16; o > 0; o >>= 1) v = max(v, __shfl_xor_sync(0xffffffffu, v, o));
        if (tid == 0) smax[0] = v;
        qrow[tid] = q[(tid << 9) + t];
    }
    __syncthreads();
    if (t >= smax[0]) return;               // never consumed (g_Y stays zero there)

    #pragma unroll
    for (int i = 0; i < 32; ++i) {
        int idx = tid + (i << 8);
        int b = idx >> 8, k = idx & 255;
        XT[b * XT_PAD + k] = we[(((size_t)qrow[b]) << 8) + k];
    }
    __syncthreads();
    float xbuf[32];
    #pragma unroll
    for (int i = 0; i < 32; ++i) {
        int idx = tid + (i << 8);
        int k = idx >> 5, b = idx & 31;
        xbuf[i] = XT[b * XT_PAD + k];
    }
    __syncthreads();
    #pragma unroll
    for (int i = 0; i < 32; ++i) {
        int idx = tid + (i << 8);
        int k = idx >> 5, b = idx & 31;
        XD[k * 32 + b] = xbuf[i];
    }
    __syncthreads();

    const int bq = tid & 3;
    const int cq = tid >> 2;

    #pragma unroll
    for (int pc = 0; pc < 2; ++pc) {
        #pragma unroll
        for (int i = 0; i < 8; ++i) {
            int u = tid + (i << 8);
            int kk = u >> 7, c16 = u & 127;
            cp16(smu + (uint32_t)((ZWB_OFF + pc * 8192 + kk * 512 + (c16 << 2)) * 4),
                 W + ((size_t)(pc * 16 + kk)) * 2048 + c0 + (c16 << 2));
        }
        cp_commit();
    }

    ull acc[4][8];
    #pragma unroll
    for (int i = 0; i < 4; ++i)
        #pragma unroll
        for (int j = 0; j < 8; ++j) acc[i][j] = 0ull;

    for (int kc = 0; kc < 16; ++kc) {
        if (kc < 15) { CP_WAIT(1); } else { CP_WAIT(0); }
        __syncthreads();
        const float* Wc = WB + (kc % 3) * 8192;
        const float* Xc = XD + kc * 16 * 32;
        #pragma unroll
        for (int kk = 0; kk < 16; ++kk) {
            ulonglong2 xa = *(const ulonglong2*)(Xc + kk * 32 + bq * 8);
            ulonglong2 xb = *(const ulonglong2*)(Xc + kk * 32 + bq * 8 + 4);
            float4 w0 = *(const float4*)(Wc + kk * 512 + cq * 8);
            float4 w1 = *(const float4*)(Wc + kk * 512 + cq * 8 + 4);
            ull ws[8];
            ws[0] = splat2_(w0.x); ws[1] = splat2_(w0.y);
            ws[2] = splat2_(w0.z); ws[3] = splat2_(w0.w);
            ws[4] = splat2_(w1.x); ws[5] = splat2_(w1.y);
            ws[6] = splat2_(w1.z); ws[7] = splat2_(w1.w);
            #pragma unroll
            for (int c = 0; c < 8; ++c) {
                acc[0][c] = ffma2_(xa.x, ws[c], acc[0][c]);
                acc[1][c] = ffma2_(xa.y, ws[c], acc[1][c]);
                acc[2][c] = ffma2_(xb.x, ws[c], acc[2][c]);
                acc[3][c] = ffma2_(xb.y, ws[c], acc[3][c]);
            }
        }
        if (kc + 2 < 16) {
            int buf = (kc + 2) % 3;
            #pragma unroll
            for (int i = 0; i < 8; ++i) {
                int u = tid + (i << 8);
                int kk = u >> 7, c16 = u & 127;
                cp16(smu + (uint32_t)((ZWB_OFF + buf * 8192 + kk * 512 + (c16 << 2)) * 4),
                     W + ((size_t)((kc + 2) * 16 + kk)) * 2048 + c0 + (c16 << 2));
            }
            cp_commit();
        }
    }

    #pragma unroll
    for (int c = 0; c < 8; ++c) {
        int cg = c0 + cq * 8 + c;
        float bb = __ldg(&bvec[cg]);
        float* outp = g_Zx + ((size_t)t * 2048 + cg) * 32 + bq * 8;
        #pragma unroll
        for (int bp = 0; bp < 4; ++bp) {
            union { ull u; float2 f; } v; v.u = acc[bp][c];
            v.f.x += bb; v.f.y += bb;
            *(float2*)(outp + bp * 2) = v.f;
        }
    }
}

// ================================================================================
// Phase B: recurrence. 2 groups x 64 blocks; block = 8 hd x 32 cols x 16 batches.
// Per-warp early release (4 arrivals/block); early exit at group t_max.
// ================================================================================
#define WD_FLT   0                        // u64[512 k][32 pos] = 32768 floats
#define ZXS_FLT  32768                    // 2 x [32 c][16 b] = 1024
#define ZR_FLT   (ZXS_FLT + 1024)         // 33792 : [8 ws][32 c][16 b] = 4096
#define LEN_FLT  (ZR_FLT + 4096)          // 37888 : [16] ints
#define SMEM_TOTAL ((LEN_FLT + 16) * 4)   // 151616 B

__global__ void __launch_bounds__(NT, 1)
lstm_kernel(const int* __restrict__ lengths, const float* __restrict__ W)
{
    extern __shared__ float sm[];
    ull*   WDu  = (ull*)(sm + WD_FLT);
    float* zxs  = sm + ZXS_FLT;
    float* zred = sm + ZR_FLT;
    int*   ls   = (int*)(sm + LEN_FLT);
    const uint32_t smu = (uint32_t)__cvta_generic_to_shared(sm);

    const int tid = threadIdx.x;
    const int bid = blockIdx.x;
    const int grp = bid >> 6;
    const int gb  = bid & 63;
    const int hd0 = gb << 3;

    // prologue: duplicated+reordered W slice (rows 256..767, block's 32 cols)
    for (int i = tid; i < 512 * 32; i += NT) {
        int k = i >> 5, c = i & 31;
        int cq = c >> 2, cc = c & 3;
        int pos = ((cc >> 1) << 4) + (cq << 1) + (cc & 1);
        float w = W[((size_t)(256 + k)) * 2048 + (((c >> 3) << 9) + hd0 + (c & 7))];
        WDu[(k << 5) + pos] = splat2_(w);
    }
    if (tid < 16) ls[tid] = lengths[(grp << 4) + tid];
    __syncthreads();

    int tmax = ls[0];
    #pragma unroll
    for (int i = 1; i < 16; ++i) tmax = max(tmax, ls[i]);

    // zx(0) prefetch into buf 0
    if (tid < 128) {
        int r = tid >> 2, p = tid & 3;
        int gcol = ((r >> 3) << 9) + hd0 + (r & 7);
        cp16(smu + (uint32_t)((ZXS_FLT + (r << 4) + (p << 2)) * 4),
             g_Zx + (size_t)gcol * 32 + (grp << 4) + (p << 2));
    }
    cp_commit();

    const int wid  = tid >> 5, lane = tid & 31;
    const int bg   = lane & 3;
    const int cq   = lane >> 2;
    const int krow0 = wid << 6;

    // persistent gate-thread state (tid < 128)
    const int gbb = tid & 15, gjj = tid >> 4;
    const int mylen = (tid < 128) ? ls[gbb] : 0;
    float c_st = 0.f, h_st = 0.f;

    unsigned* barp = &g_barc[grp << 5];

    for (int t = 0; t < tmax; ++t) {
        // ---- issue zx(t+1) into the other buffer ----
        if (t + 1 < tmax && tid < 128) {
            int r = tid >> 2, p = tid & 3;
            int gcol = ((r >> 3) << 9) + hd0 + (r & 7);
            cp16(smu + (uint32_t)((ZXS_FLT + (((t + 1) & 1) << 9) + (r << 4) + (p << 2)) * 4),
                 g_Zx + ((size_t)((t + 1) << 11) + gcol) * 32 + (grp << 4) + (p << 2));
        }
        cp_commit();

        // ---- h-GEMM: h LDG-direct from L2 (.cg — bypass stale L1) ----
        const float* hp = g_hT + (((grp << 1) + (t & 1)) << 13)
                          + (krow0 << 4) + (bg << 2);
        const ull* Wc = WDu + (krow0 << 5);
        ull a0 = 0ull, a1 = 0ull, a2 = 0ull, a3 = 0ull;
        ull a4 = 0ull, a5 = 0ull, a6 = 0ull, a7 = 0ull;
        #pragma unroll 8
        for (int kk = 0; kk < 64; ++kk) {
            ull hx, hy;
            asm("ld.global.cg.v2.u64 {%0, %1}, [%2];"
                : "=l"(hx), "=l"(hy) : "l"(hp + (kk << 4)));
            ulonglong2 w0 = *(const ulonglong2*)(Wc + (kk << 5) + (cq << 1));
            ulonglong2 w1 = *(const ulonglong2*)(Wc + (kk << 5) + 16 + (cq << 1));
            a0 = ffma2_(hx, w0.x, a0);
            a1 = ffma2_(hy, w0.x, a1);
            a2 = ffma2_(hx, w0.y, a2);
            a3 = ffma2_(hy, w0.y, a3);
            a4 = ffma2_(hx, w1.x, a4);
            a5 = ffma2_(hy, w1.x, a5);
            a6 = ffma2_(hx, w1.y, a6);
            a7 = ffma2_(hy, w1.y, a7);
        }
        {
            ull* zru = (ull*)zred;
            int base0 = (((wid << 5) + (cq << 2)) << 3) + (bg << 1);
            zru[base0]      = a0;  zru[base0 + 1]  = a1;
            zru[base0 + 8]  = a2;  zru[base0 + 9]  = a3;
            zru[base0 + 16] = a4;  zru[base0 + 17] = a5;
            zru[base0 + 24] = a6;  zru[base0 + 25] = a7;
        }
        CP_WAIT(1);
        __syncthreads();

        // ---- gates + state update (128 threads; state in regs) ----
        if (tid < 128) {
            const float* zx_t = zxs + ((t & 1) << 9);
            float gt[4];
            #pragma unroll
            for (int gate = 0; gate < 4; ++gate) {
                int c = (gate << 3) + gjj;
                float s = zx_t[(c << 4) + gbb];
                #pragma unroll
                for (int ks = 0; ks < 8; ++ks) s += zred[(((ks << 5) + c) << 4) + gbb];
                gt[gate] = s;
            }
            float i_ = fsig_(gt[0]);
            float jt = ftanh_(gt[1]);
            float f_ = fsig_(gt[2] + 1.f);
            float o_ = fsig_(gt[3]);
            float cnew = c_st * f_ + i_ * jt;
            float hnew = ftanh_(cnew) * o_;
            bool m = t < mylen;
            c_st = m ? cnew : c_st;
            float hout = m ? hnew : h_st;
            h_st = hout;
            int hd = hd0 + gjj;
            g_hT[(((grp << 1) + ((t + 1) & 1)) << 13) + (hd << 4) + gbb] = hout;
            g_Y[((size_t)(t << 9) + hd) * 32 + (grp << 4) + gbb] = m ? hnew : 0.f;
            // ---- per-warp early release: this warp's h rows are stored ----
            __syncwarp();
            if ((tid & 31) == 0) {
                asm volatile("red.release.gpu.global.add.u32 [%0], %1;"
                             :: "l"(barp), "r"(1u) : "memory");
            }
        }

        // ---- single poller waits for all 256 arrivals of this step ----
        if (tid == 0) {
            unsigned target = ((unsigned)(t + 1)) << 8;   // 64 blocks * 4 warps
            unsigned v;
            do {
                asm volatile("ld.acquire.gpu.global.u32 %0, [%1];"
                             : "=r"(v) : "l"(barp) : "memory");
            } while (v < target);
        }
        __syncthreads();
    }
}

// ================================================================================
// Phase C: projection + masked xent. one block per t
// ================================================================================
#define LS_YS   0
#define LS_PW   16384
#define LS_LG   (16384 + 25600)
#define LOSS_SMEM ((LS_LG + 1600) * 4)

__global__ void __launch_bounds__(256, 1)
loss_kernel(const int* __restrict__ a, const int* __restrict__ lengths,
            const float* __restrict__ pW, const float* __restrict__ pb)
{
    extern __shared__ float lsm[];
    float* ys  = lsm + LS_YS;
    float* pWs = lsm + LS_PW;
    float* lg  = lsm + LS_LG;
    const int t = blockIdx.x;
    const int tid = threadIdx.x;

    {
        const float4* src = (const float4*)(g_Y + (size_t)t * (H_ * B_));
        float4* dst = (float4*)ys;
        #pragma unroll
        for (int i = 0; i < 16; ++i) dst[tid + i * 256] = src[tid + i * 256];
        const float4* ps = (const float4*)pW;
        float4* pd = (float4*)pWs;
        #pragma unroll
        for (int i = 0; i < 25; ++i) pd[tid + i * 256] = ps[tid + i * 256];
    }
    __syncthreads();

    {
        int b = tid & 31, l0 = tid >> 5;
        for (int l = l0; l < 50; l += 8) {
            float s = __ldg(&pb[l]);
            #pragma unroll 8
            for (int h = 0; h < 512; ++h) s += ys[h * 32 + b] * pWs[h * 50 + l];
            lg[l * 32 + b] = fmaxf(s, 0.f);
        }
    }
    __syncthreads();

    if (tid < 32) {
        int b = tid;
        if (t < __ldg(&lengths[b])) {
            float mx = lg[b];
            #pragma unroll
            for (int l = 1; l < 50; ++l) mx = fmaxf(mx, lg[l * 32 + b]);
            float se = 0.f;
            #pragma unroll
            for (int l = 0; l < 50; ++l) se += expf(lg[l * 32 + b] - mx);
            float lse = logf(se) + mx;
            int lab = __ldg(&a[(b << 9) + t]);
            atomicAdd(&g_acc[b], lse - lg[lab * 32 + b]);
        }
    }
}

__global__ void final_kernel(const int* __restrict__ lengths, float* __restrict__ out) {
    if (threadIdx.x == 0) {
        float s = 0.f;
        for (int b = 0; b < B_; ++b) s += g_acc[b] / (float)lengths[b];
        out[0] = s * (1.f / (float)B_);
    }
}

// ---------------- launch ----------------------------------------------------------
extern "C" void kernel_launch(void* const* d_in, const int* in_sizes, int n_in,
                              void* d_out, int out_size) {
    const int*   q       = (const int*)d_in[0];
    const int*   a       = (const int*)d_in[1];
    const int*   lengths = (const int*)d_in[2];
    const float* we      = (const float*)d_in[3];
    const float* W       = (const float*)d_in[4];
    const float* bvec    = (const float*)d_in[5];
    const float* pW      = (const float*)d_in[6];
    const float* pb      = (const float*)d_in[7];
    float* out = (float*)d_out;

    cudaFuncSetAttribute(zx_kernel, cudaFuncAttributeMaxDynamicSharedMemorySize, ZX_SMEM);
    cudaFuncSetAttribute(lstm_kernel, cudaFuncAttributeMaxDynamicSharedMemorySize, SMEM_TOTAL);
    cudaFuncSetAttribute(loss_kernel, cudaFuncAttributeMaxDynamicSharedMemorySize, LOSS_SMEM);

    zx_kernel<<<T_ * 4, 256, ZX_SMEM>>>(q, we, W, bvec, lengths);
    lstm_kernel<<<NBLK, NT, SMEM_TOTAL>>>(lengths, W);
    loss_kernel<<<T_, 256, LOSS_SMEM>>>(a, lengths, pW, pb);
    final_kernel<<<1, 32>>>(lengths, out);
}

// round 12
// speedup vs baseline: 1.2574x; 1.2574x over previous
#include <cuda_runtime.h>
#include <math.h>
#include <stdint.h>

#define B_   32
#define T_   512
#define E_   256
#define H_   512
#define L_   50
#define NT   512     // 16 warps: latency hiding for the recurrence
#define NBLK 128     // recurrent blocks, 1/SM
#define NBG  64      // blocks per batch-group

typedef unsigned long long ull;

// ---------------- device globals -----------------------------------------------
__device__ __align__(16) float g_hT[2 * 2 * H_ * 16];   // [grp][buf][hd][16b]
__device__ __align__(16) float g_Y[T_ * H_ * B_];       // [t][hd][32b] (zero-init .bss)
__device__ __align__(16) float g_Zx[(size_t)T_ * 2048 * B_]; // [t][col][32b]
__device__ float g_acc[B_];
__device__ unsigned g_barc[2 * 32];                     // per-group counters, 128B apart

// ---------------- helpers --------------------------------------------------------
__device__ __forceinline__ ull ffma2_(ull a, ull b, ull c) {
    ull d;
    asm("fma.rn.f32x2 %0, %1, %2, %3;" : "=l"(d) : "l"(a), "l"(b), "l"(c));
    return d;
}
__device__ __forceinline__ ull splat2_(float x) {
    ull r; unsigned xi = __float_as_uint(x);
    asm("mov.b64 %0, {%1, %1};" : "=l"(r) : "r"(xi));
    return r;
}
__device__ __forceinline__ void cp16(uint32_t dst, const void* src) {
    asm volatile("cp.async.cg.shared.global [%0], [%1], 16;" :: "r"(dst), "l"(src));
}
__device__ __forceinline__ void cp_commit() { asm volatile("cp.async.commit_group;"); }
#define CP_WAIT(N) asm volatile("cp.async.wait_group %0;" :: "n"(N) : "memory")

__device__ __forceinline__ float fsig_(float x) {
    x = fminf(fmaxf(x, -30.f), 30.f);
    float e = __expf(-x);
    return __fdividef(1.f, 1.f + e);
}
__device__ __forceinline__ float ftanh_(float x) {
    x = fminf(fmaxf(x, -15.f), 15.f);
    float e = __expf(-2.f * x);
    return __fdividef(1.f - e, 1.f + e);
}

// ================================================================================
// Phase A: zx precompute.  grid = (T_ * 4); block 0 also resets state.
// ================================================================================
#define ZXD_OFF  0
#define ZWB_OFF  (256*32)
#define ZX_SMEM  ((8192 + 3*8192) * 4)
#define XT_PAD   261

__global__ void __launch_bounds__(256, 1)
zx_kernel(const int* __restrict__ q, const float* __restrict__ we,
          const float* __restrict__ W, const float* __restrict__ bvec,
          const int* __restrict__ lengths)
{
    extern __shared__ float sm[];
    float* XD = sm + ZXD_OFF;
    float* WB = sm + ZWB_OFF;
    float* XT = sm + ZWB_OFF;
    const uint32_t smu = (uint32_t)__cvta_generic_to_shared(sm);
    __shared__ int qrow[32];
    __shared__ int smax[1];

    const int tid = threadIdx.x;
    const int t   = blockIdx.x >> 2;
    const int c0  = (blockIdx.x & 3) << 9;

    if (blockIdx.x == 0) {                  // graph-replay-safe reset
        if (tid < 64) g_barc[tid] = 0u;
        if (tid < 32) g_acc[tid] = 0.f;
        float4 z4 = make_float4(0.f, 0.f, 0.f, 0.f);
        float4* hp4 = (float4*)g_hT;
        #pragma unroll
        for (int i = 0; i < 32; ++i) hp4[tid + (i << 8)] = z4;   // 32768 floats
    }

    if (tid < 32) {
        int v = lengths[tid];
        #pragma unroll
        for (int o = 16; o > 0; o >>= 1) v = max(v, __shfl_xor_sync(0xffffffffu, v, o));
        if (tid == 0) smax[0] = v;
        qrow[tid] = q[(tid << 9) + t];
    }
    __syncthreads();
    if (t >= smax[0]) return;               // never consumed (g_Y stays zero there)

    #pragma unroll
    for (int i = 0; i < 32; ++i) {
        int idx = tid + (i << 8);
        int b = idx >> 8, k = idx & 255;
        XT[b * XT_PAD + k] = we[(((size_t)qrow[b]) << 8) + k];
    }
    __syncthreads();
    float xbuf[32];
    #pragma unroll
    for (int i = 0; i < 32; ++i) {
        int idx = tid + (i << 8);
        int k = idx >> 5, b = idx & 31;
        xbuf[i] = XT[b * XT_PAD + k];
    }
    __syncthreads();
    #pragma unroll
    for (int i = 0; i < 32; ++i) {
        int idx = tid + (i << 8);
        int k = idx >> 5, b = idx & 31;
        XD[k * 32 + b] = xbuf[i];
    }
    __syncthreads();

    const int bq = tid & 3;
    const int cq = tid >> 2;

    #pragma unroll
    for (int pc = 0; pc < 2; ++pc) {
        #pragma unroll
        for (int i = 0; i < 8; ++i) {
            int u = tid + (i << 8);
            int kk = u >> 7, c16 = u & 127;
            cp16(smu + (uint32_t)((ZWB_OFF + pc * 8192 + kk * 512 + (c16 << 2)) * 4),
                 W + ((size_t)(pc * 16 + kk)) * 2048 + c0 + (c16 << 2));
        }
        cp_commit();
    }

    ull acc[4][8];
    #pragma unroll
    for (int i = 0; i < 4; ++i)
        #pragma unroll
        for (int j = 0; j < 8; ++j) acc[i][j] = 0ull;

    for (int kc = 0; kc < 16; ++kc) {
        if (kc < 15) { CP_WAIT(1); } else { CP_WAIT(0); }
        __syncthreads();
        const float* Wc = WB + (kc % 3) * 8192;
        const float* Xc = XD + kc * 16 * 32;
        #pragma unroll
        for (int kk = 0; kk < 16; ++kk) {
            ulonglong2 xa = *(const ulonglong2*)(Xc + kk * 32 + bq * 8);
            ulonglong2 xb = *(const ulonglong2*)(Xc + kk * 32 + bq * 8 + 4);
            float4 w0 = *(const float4*)(Wc + kk * 512 + cq * 8);
            float4 w1 = *(const float4*)(Wc + kk * 512 + cq * 8 + 4);
            ull ws[8];
            ws[0] = splat2_(w0.x); ws[1] = splat2_(w0.y);
            ws[2] = splat2_(w0.z); ws[3] = splat2_(w0.w);
            ws[4] = splat2_(w1.x); ws[5] = splat2_(w1.y);
            ws[6] = splat2_(w1.z); ws[7] = splat2_(w1.w);
            #pragma unroll
            for (int c = 0; c < 8; ++c) {
                acc[0][c] = ffma2_(xa.x, ws[c], acc[0][c]);
                acc[1][c] = ffma2_(xa.y, ws[c], acc[1][c]);
                acc[2][c] = ffma2_(xb.x, ws[c], acc[2][c]);
                acc[3][c] = ffma2_(xb.y, ws[c], acc[3][c]);
            }
        }
        if (kc + 2 < 16) {
            int buf = (kc + 2) % 3;
            #pragma unroll
            for (int i = 0; i < 8; ++i) {
                int u = tid + (i << 8);
                int kk = u >> 7, c16 = u & 127;
                cp16(smu + (uint32_t)((ZWB_OFF + buf * 8192 + kk * 512 + (c16 << 2)) * 4),
                     W + ((size_t)((kc + 2) * 16 + kk)) * 2048 + c0 + (c16 << 2));
            }
            cp_commit();
        }
    }

    #pragma unroll
    for (int c = 0; c < 8; ++c) {
        int cg = c0 + cq * 8 + c;
        float bb = __ldg(&bvec[cg]);
        float* outp = g_Zx + ((size_t)t * 2048 + cg) * 32 + bq * 8;
        #pragma unroll
        for (int bp = 0; bp < 4; ++bp) {
            union { ull u; float2 f; } v; v.u = acc[bp][c];
            v.f.x += bb; v.f.y += bb;
            *(float2*)(outp + bp * 2) = v.f;
        }
    }
}

// ================================================================================
// Phase B: recurrence. 2 groups x 64 blocks; block = 8 hd x 32 cols x 16 batches.
// 512 threads / 16 warps (4 per SMSP) for latency hiding; sync shape = round 9.
// ================================================================================
#define WD_FLT   0                        // u64[512 k][32 pos] = 32768 floats
#define ZXS_FLT  32768                    // 2 x [32 c][16 b] = 1024
#define ZR_FLT   (ZXS_FLT + 1024)         // 33792 : [16 ws][32 c][16 b] = 8192
#define LEN_FLT  (ZR_FLT + 8192)          // 41984 : [16] ints
#define SMEM_TOTAL ((LEN_FLT + 16) * 4)   // 168000 B

__global__ void __launch_bounds__(NT, 1)
lstm_kernel(const int* __restrict__ lengths, const float* __restrict__ W)
{
    extern __shared__ float sm[];
    ull*   WDu  = (ull*)(sm + WD_FLT);
    float* zxs  = sm + ZXS_FLT;
    float* zred = sm + ZR_FLT;
    int*   ls   = (int*)(sm + LEN_FLT);
    const uint32_t smu = (uint32_t)__cvta_generic_to_shared(sm);

    const int tid = threadIdx.x;
    const int bid = blockIdx.x;
    const int grp = bid >> 6;
    const int gb  = bid & 63;
    const int hd0 = gb << 3;

    // prologue: duplicated+reordered W slice (rows 256..767, block's 32 cols)
    for (int i = tid; i < 512 * 32; i += NT) {
        int k = i >> 5, c = i & 31;
        int cq = c >> 2, cc = c & 3;
        int pos = ((cc >> 1) << 4) + (cq << 1) + (cc & 1);
        float w = W[((size_t)(256 + k)) * 2048 + (((c >> 3) << 9) + hd0 + (c & 7))];
        WDu[(k << 5) + pos] = splat2_(w);
    }
    if (tid < 16) ls[tid] = lengths[(grp << 4) + tid];
    __syncthreads();

    int tmax = ls[0];
    #pragma unroll
    for (int i = 1; i < 16; ++i) tmax = max(tmax, ls[i]);

    // zx(0) prefetch into buf 0
    if (tid < 128) {
        int r = tid >> 2, p = tid & 3;
        int gcol = ((r >> 3) << 9) + hd0 + (r & 7);
        cp16(smu + (uint32_t)((ZXS_FLT + (r << 4) + (p << 2)) * 4),
             g_Zx + (size_t)gcol * 32 + (grp << 4) + (p << 2));
    }
    cp_commit();

    const int wid  = tid >> 5, lane = tid & 31;
    const int bg   = lane & 3;
    const int cq   = lane >> 2;
    const int krow0 = wid << 5;            // 32 k-rows per warp (16 warps)

    // persistent gate-thread state (tid < 128)
    const int gbb = tid & 15, gjj = (tid >> 4) & 7;
    const int mylen = ls[gbb];
    float c_st = 0.f, h_st = 0.f;

    unsigned* barp = &g_barc[grp << 5];

    for (int t = 0; t < tmax; ++t) {
        // ---- issue zx(t+1) into the other buffer ----
        if (t + 1 < tmax && tid < 128) {
            int r = tid >> 2, p = tid & 3;
            int gcol = ((r >> 3) << 9) + hd0 + (r & 7);
            cp16(smu + (uint32_t)((ZXS_FLT + (((t + 1) & 1) << 9) + (r << 4) + (p << 2)) * 4),
                 g_Zx + ((size_t)((t + 1) << 11) + gcol) * 32 + (grp << 4) + (p << 2));
        }
        cp_commit();

        // ---- h-GEMM: 32 k-rows per warp, h LDG-direct from L2 (.cg) ----
        const float* hp = g_hT + (((grp << 1) + (t & 1)) << 13)
                          + (krow0 << 4) + (bg << 2);
        const ull* Wc = WDu + (krow0 << 5);
        ull a0 = 0ull, a1 = 0ull, a2 = 0ull, a3 = 0ull;
        ull a4 = 0ull, a5 = 0ull, a6 = 0ull, a7 = 0ull;
        #pragma unroll 8
        for (int kk = 0; kk < 32; ++kk) {
            ull hx, hy;
            asm("ld.global.cg.v2.u64 {%0, %1}, [%2];"
                : "=l"(hx), "=l"(hy) : "l"(hp + (kk << 4)));
            ulonglong2 w0 = *(const ulonglong2*)(Wc + (kk << 5) + (cq << 1));
            ulonglong2 w1 = *(const ulonglong2*)(Wc + (kk << 5) + 16 + (cq << 1));
            a0 = ffma2_(hx, w0.x, a0);
            a1 = ffma2_(hy, w0.x, a1);
            a2 = ffma2_(hx, w0.y, a2);
            a3 = ffma2_(hy, w0.y, a3);
            a4 = ffma2_(hx, w1.x, a4);
            a5 = ffma2_(hy, w1.x, a5);
            a6 = ffma2_(hx, w1.y, a6);
            a7 = ffma2_(hy, w1.y, a7);
        }
        {
            ull* zru = (ull*)zred;
            int base0 = (((wid << 5) + (cq << 2)) << 3) + (bg << 1);
            zru[base0]      = a0;  zru[base0 + 1]  = a1;
            zru[base0 + 8]  = a2;  zru[base0 + 9]  = a3;
            zru[base0 + 16] = a4;  zru[base0 + 17] = a5;
            zru[base0 + 24] = a6;  zru[base0 + 25] = a7;
        }
        CP_WAIT(1);
        __syncthreads();

        // ---- gates + state update (128 threads; state in regs) ----
        if (tid < 128) {
            const float* zx_t = zxs + ((t & 1) << 9);
            float gt[4];
            #pragma unroll
            for (int gate = 0; gate < 4; ++gate) {
                int c = (gate << 3) + gjj;
                float s = zx_t[(c << 4) + gbb];
                #pragma unroll
                for (int ks = 0; ks < 16; ++ks) s += zred[(((ks << 5) + c) << 4) + gbb];
                gt[gate] = s;
            }
            float i_ = fsig_(gt[0]);
            float jt = ftanh_(gt[1]);
            float f_ = fsig_(gt[2] + 1.f);
            float o_ = fsig_(gt[3]);
            float cnew = c_st * f_ + i_ * jt;
            float hnew = ftanh_(cnew) * o_;
            bool m = t < mylen;
            c_st = m ? cnew : c_st;
            float hout = m ? hnew : h_st;
            h_st = hout;
            int hd = hd0 + gjj;
            g_hT[(((grp << 1) + ((t + 1) & 1)) << 13) + (hd << 4) + gbb] = hout;
            g_Y[((size_t)(t << 9) + hd) * 32 + (grp << 4) + gbb] = m ? hnew : 0.f;
        }
        __syncthreads();

        // ---- group barrier: one arrive per block, single poller (round-9 shape) ----
        if (tid == 0) {
            asm volatile("red.release.gpu.global.add.u32 [%0], %1;"
                         :: "l"(barp), "r"(1u) : "memory");
            unsigned target = (unsigned)(t + 1) * NBG;
            unsigned v;
            do {
                asm volatile("ld.acquire.gpu.global.u32 %0, [%1];"
                             : "=r"(v) : "l"(barp) : "memory");
            } while (v < target);
        }
        __syncthreads();
    }
}

// ================================================================================
// Phase C: projection + masked xent. one block per t
// ================================================================================
#define LS_YS   0
#define LS_PW   16384
#define LS_LG   (16384 + 25600)
#define LOSS_SMEM ((LS_LG + 1600) * 4)

__global__ void __launch_bounds__(256, 1)
loss_kernel(const int* __restrict__ a, const int* __restrict__ lengths,
            const float* __restrict__ pW, const float* __restrict__ pb)
{
    extern __shared__ float lsm[];
    float* ys  = lsm + LS_YS;
    float* pWs = lsm + LS_PW;
    float* lg  = lsm + LS_LG;
    const int t = blockIdx.x;
    const int tid = threadIdx.x;

    {
        const float4* src = (const float4*)(g_Y + (size_t)t * (H_ * B_));
        float4* dst = (float4*)ys;
        #pragma unroll
        for (int i = 0; i < 16; ++i) dst[tid + i * 256] = src[tid + i * 256];
        const float4* ps = (const float4*)pW;
        float4* pd = (float4*)pWs;
        #pragma unroll
        for (int i = 0; i < 25; ++i) pd[tid + i * 256] = ps[tid + i * 256];
    }
    __syncthreads();

    {
        int b = tid & 31, l0 = tid >> 5;
        for (int l = l0; l < 50; l += 8) {
            float s = __ldg(&pb[l]);
            #pragma unroll 8
            for (int h = 0; h < 512; ++h) s += ys[h * 32 + b] * pWs[h * 50 + l];
            lg[l * 32 + b] = fmaxf(s, 0.f);
        }
    }
    __syncthreads();

    if (tid < 32) {
        int b = tid;
        if (t < __ldg(&lengths[b])) {
            float mx = lg[b];
            #pragma unroll
            for (int l = 1; l < 50; ++l) mx = fmaxf(mx, lg[l * 32 + b]);
            float se = 0.f;
            #pragma unroll
            for (int l = 0; l < 50; ++l) se += expf(lg[l * 32 + b] - mx);
            float lse = logf(se) + mx;
            int lab = __ldg(&a[(b << 9) + t]);
            atomicAdd(&g_acc[b], lse - lg[lab * 32 + b]);
        }
    }
}

__global__ void final_kernel(const int* __restrict__ lengths, float* __restrict__ out) {
    if (threadIdx.x == 0) {
        float s = 0.f;
        for (int b = 0; b < B_; ++b) s += g_acc[b] / (float)lengths[b];
        out[0] = s * (1.f / (float)B_);
    }
}

// ---------------- launch ----------------------------------------------------------
extern "C" void kernel_launch(void* const* d_in, const int* in_sizes, int n_in,
                              void* d_out, int out_size) {
    const int*   q       = (const int*)d_in[0];
    const int*   a       = (const int*)d_in[1];
    const int*   lengths = (const int*)d_in[2];
    const float* we      = (const float*)d_in[3];
    const float* W       = (const float*)d_in[4];
    const float* bvec    = (const float*)d_in[5];
    const float* pW      = (const float*)d_in[6];
    const float* pb      = (const float*)d_in[7];
    float* out = (float*)d_out;

    cudaFuncSetAttribute(zx_kernel, cudaFuncAttributeMaxDynamicSharedMemorySize, ZX_SMEM);
    cudaFuncSetAttribute(lstm_kernel, cudaFuncAttributeMaxDynamicSharedMemorySize, SMEM_TOTAL);
    cudaFuncSetAttribute(loss_kernel, cudaFuncAttributeMaxDynamicSharedMemorySize, LOSS_SMEM);

    zx_kernel<<<T_ * 4, 256, ZX_SMEM>>>(q, we, W, bvec, lengths);
    lstm_kernel<<<NBLK, NT, SMEM_TOTAL>>>(lengths, W);
    loss_kernel<<<T_, 256, LOSS_SMEM>>>(a, lengths, pW, pb);
    final_kernel<<<1, 32>>>(lengths, out);
}

// round 13
// speedup vs baseline: 1.3167x; 1.0472x over previous
#include <cuda_runtime.h>
#include <math.h>
#include <stdint.h>

#define B_   32
#define T_   512
#define E_   256
#define H_   512
#define L_   50
#define NT   512     // 16 warps
#define NBLK 128     // recurrent blocks, 1/SM
#define GPB  32      // blocks per batch-group (4 groups of 8 batches)

typedef unsigned long long ull;

// ---------------- device globals -----------------------------------------------
__device__ __align__(16) float g_hT[4 * 2 * H_ * 8];    // [grp][buf][hd][8b]
__device__ __align__(16) float g_Y[T_ * H_ * B_];       // [t][hd][32b] (zero-init .bss)
__device__ __align__(16) float g_Zx[(size_t)T_ * 2048 * B_]; // [t][col][32b]
__device__ float g_acc[B_];
__device__ unsigned g_barc[4 * 32];                     // per-group counters, 128B apart

// ---------------- helpers --------------------------------------------------------
__device__ __forceinline__ ull ffma2_(ull a, ull b, ull c) {
    ull d;
    asm("fma.rn.f32x2 %0, %1, %2, %3;" : "=l"(d) : "l"(a), "l"(b), "l"(c));
    return d;
}
__device__ __forceinline__ ull splat2_(float x) {
    ull r; unsigned xi = __float_as_uint(x);
    asm("mov.b64 %0, {%1, %1};" : "=l"(r) : "r"(xi));
    return r;
}
__device__ __forceinline__ void cp16(uint32_t dst, const void* src) {
    asm volatile("cp.async.cg.shared.global [%0], [%1], 16;" :: "r"(dst), "l"(src));
}
__device__ __forceinline__ void cp_commit() { asm volatile("cp.async.commit_group;"); }
#define CP_WAIT(N) asm volatile("cp.async.wait_group %0;" :: "n"(N) : "memory")

__device__ __forceinline__ float fsig_(float x) {
    x = fminf(fmaxf(x, -30.f), 30.f);
    float e = __expf(-x);
    return __fdividef(1.f, 1.f + e);
}
__device__ __forceinline__ float ftanh_(float x) {
    x = fminf(fmaxf(x, -15.f), 15.f);
    float e = __expf(-2.f * x);
    return __fdividef(1.f - e, 1.f + e);
}

// ================================================================================
// Phase A: zx precompute.  grid = (T_ * 4); block 0 also resets state.
// ================================================================================
#define ZXD_OFF  0
#define ZWB_OFF  (256*32)
#define ZX_SMEM  ((8192 + 3*8192) * 4)
#define XT_PAD   261

__global__ void __launch_bounds__(256, 1)
zx_kernel(const int* __restrict__ q, const float* __restrict__ we,
          const float* __restrict__ W, const float* __restrict__ bvec,
          const int* __restrict__ lengths)
{
    extern __shared__ float sm[];
    float* XD = sm + ZXD_OFF;
    float* WB = sm + ZWB_OFF;
    float* XT = sm + ZWB_OFF;
    const uint32_t smu = (uint32_t)__cvta_generic_to_shared(sm);
    __shared__ int qrow[32];
    __shared__ int smax[1];

    const int tid = threadIdx.x;
    const int t   = blockIdx.x >> 2;
    const int c0  = (blockIdx.x & 3) << 9;

    if (blockIdx.x == 0) {                  // graph-replay-safe reset
        if (tid < 128) g_barc[tid] = 0u;
        if (tid < 32)  g_acc[tid] = 0.f;
        float4 z4 = make_float4(0.f, 0.f, 0.f, 0.f);
        float4* hp4 = (float4*)g_hT;
        #pragma unroll
        for (int i = 0; i < 32; ++i) hp4[tid + (i << 8)] = z4;   // 32768 floats
    }

    if (tid < 32) {
        int v = lengths[tid];
        #pragma unroll
        for (int o = 16; o > 0; o >>= 1) v = max(v, __shfl_xor_sync(0xffffffffu, v, o));
        if (tid == 0) smax[0] = v;
        qrow[tid] = q[(tid << 9) + t];
    }
    __syncthreads();
    if (t >= smax[0]) return;               // never consumed (g_Y stays zero there)

    #pragma unroll
    for (int i = 0; i < 32; ++i) {
        int idx = tid + (i << 8);
        int b = idx >> 8, k = idx & 255;
        XT[b * XT_PAD + k] = we[(((size_t)qrow[b]) << 8) + k];
    }
    __syncthreads();
    float xbuf[32];
    #pragma unroll
    for (int i = 0; i < 32; ++i) {
        int idx = tid + (i << 8);
        int k = idx >> 5, b = idx & 31;
        xbuf[i] = XT[b * XT_PAD + k];
    }
    __syncthreads();
    #pragma unroll
    for (int i = 0; i < 32; ++i) {
        int idx = tid + (i << 8);
        int k = idx >> 5, b = idx & 31;
        XD[k * 32 + b] = xbuf[i];
    }
    __syncthreads();

    const int bq = tid & 3;
    const int cq = tid >> 2;

    #pragma unroll
    for (int pc = 0; pc < 2; ++pc) {
        #pragma unroll
        for (int i = 0; i < 8; ++i) {
            int u = tid + (i << 8);
            int kk = u >> 7, c16 = u & 127;
            cp16(smu + (uint32_t)((ZWB_OFF + pc * 8192 + kk * 512 + (c16 << 2)) * 4),
                 W + ((size_t)(pc * 16 + kk)) * 2048 + c0 + (c16 << 2));
        }
        cp_commit();
    }

    ull acc[4][8];
    #pragma unroll
    for (int i = 0; i < 4; ++i)
        #pragma unroll
        for (int j = 0; j < 8; ++j) acc[i][j] = 0ull;

    for (int kc = 0; kc < 16; ++kc) {
        if (kc < 15) { CP_WAIT(1); } else { CP_WAIT(0); }
        __syncthreads();
        const float* Wc = WB + (kc % 3) * 8192;
        const float* Xc = XD + kc * 16 * 32;
        #pragma unroll
        for (int kk = 0; kk < 16; ++kk) {
            ulonglong2 xa = *(const ulonglong2*)(Xc + kk * 32 + bq * 8);
            ulonglong2 xb = *(const ulonglong2*)(Xc + kk * 32 + bq * 8 + 4);
            float4 w0 = *(const float4*)(Wc + kk * 512 + cq * 8);
            float4 w1 = *(const float4*)(Wc + kk * 512 + cq * 8 + 4);
            ull ws[8];
            ws[0] = splat2_(w0.x); ws[1] = splat2_(w0.y);
            ws[2] = splat2_(w0.z); ws[3] = splat2_(w0.w);
            ws[4] = splat2_(w1.x); ws[5] = splat2_(w1.y);
            ws[6] = splat2_(w1.z); ws[7] = splat2_(w1.w);
            #pragma unroll
            for (int c = 0; c < 8; ++c) {
                acc[0][c] = ffma2_(xa.x, ws[c], acc[0][c]);
                acc[1][c] = ffma2_(xa.y, ws[c], acc[1][c]);
                acc[2][c] = ffma2_(xb.x, ws[c], acc[2][c]);
                acc[3][c] = ffma2_(xb.y, ws[c], acc[3][c]);
            }
        }
        if (kc + 2 < 16) {
            int buf = (kc + 2) % 3;
            #pragma unroll
            for (int i = 0; i < 8; ++i) {
                int u = tid + (i << 8);
                int kk = u >> 7, c16 = u & 127;
                cp16(smu + (uint32_t)((ZWB_OFF + buf * 8192 + kk * 512 + (c16 << 2)) * 4),
                     W + ((size_t)((kc + 2) * 16 + kk)) * 2048 + c0 + (c16 << 2));
            }
            cp_commit();
        }
    }

    #pragma unroll
    for (int c = 0; c < 8; ++c) {
        int cg = c0 + cq * 8 + c;
        float bb = __ldg(&bvec[cg]);
        float* outp = g_Zx + ((size_t)t * 2048 + cg) * 32 + bq * 8;
        #pragma unroll
        for (int bp = 0; bp < 4; ++bp) {
            union { ull u; float2 f; } v; v.u = acc[bp][c];
            v.f.x += bb; v.f.y += bb;
            *(float2*)(outp + bp * 2) = v.f;
        }
    }
}

// ================================================================================
// Phase B: recurrence. 4 groups x 32 blocks; block = 16 hd x 64 cols x 8 batches.
// W in smem non-duplicated (float4 load + splat); sync shape = round 9.
// ================================================================================
#define WD_FLT   0                        // [512 k][64 c] floats = 32768
#define ZXS_FLT  32768                    // 2 x [64 c][8 b] = 1024
#define ZR_FLT   (ZXS_FLT + 1024)         // 33792 : [16 ws][64 c][8 b] = 8192
#define LEN_FLT  (ZR_FLT + 8192)          // 41984 : [8] ints
#define SMEM_TOTAL ((LEN_FLT + 8) * 4)    // 167968 B

__global__ void __launch_bounds__(NT, 1)
lstm_kernel(const int* __restrict__ lengths, const float* __restrict__ W)
{
    extern __shared__ float sm[];
    float* Wsm  = sm + WD_FLT;
    float* zxs  = sm + ZXS_FLT;
    float* zred = sm + ZR_FLT;
    int*   ls   = (int*)(sm + LEN_FLT);
    const uint32_t smu = (uint32_t)__cvta_generic_to_shared(sm);

    const int tid = threadIdx.x;
    const int bid = blockIdx.x;
    const int grp = bid >> 5;              // 4 groups
    const int gb  = bid & 31;
    const int hd0 = gb << 4;               // 16 h-dims per block

    // prologue: W slice (rows 256..767, block's 64 cols), layout [k][64c]
    for (int i = tid; i < 512 * 64; i += NT) {
        int k = i >> 6, c = i & 63;        // c = gate*16 + jj
        Wsm[i] = W[((size_t)(256 + k)) * 2048 + (((c >> 4) << 9) + hd0 + (c & 15))];
    }
    if (tid < 8) ls[tid] = lengths[(grp << 3) + tid];
    __syncthreads();

    int tmax = ls[0];
    #pragma unroll
    for (int i = 1; i < 8; ++i) tmax = max(tmax, ls[i]);

    // zx(0) prefetch into buf 0: 64 cols x 8 floats = 128 cp16
    if (tid < 128) {
        int r = tid >> 1, p = tid & 1;     // col r, 16B half p
        int gcol = ((r >> 4) << 9) + hd0 + (r & 15);
        cp16(smu + (uint32_t)((ZXS_FLT + (r << 3) + (p << 2)) * 4),
             g_Zx + (size_t)gcol * 32 + (grp << 3) + (p << 2));
    }
    cp_commit();

    const int wid  = tid >> 5, lane = tid & 31;
    const int bg   = lane & 1;             // batch quad: b = 4bg..4bg+3
    const int cw   = lane >> 1;            // col quad:  c = 4cw..4cw+3
    const int krow0 = wid << 5;            // 32 k-rows per warp

    // persistent gate-thread state (tid < 128): b = tid&7, jj = tid>>3 (0..15)
    const int gbb = tid & 7, gjj = (tid >> 3) & 15;
    const int mylen = ls[gbb];
    float c_st = 0.f, h_st = 0.f;

    unsigned* barp = &g_barc[grp << 5];

    for (int t = 0; t < tmax; ++t) {
        // ---- issue zx(t+1) into the other buffer ----
        if (t + 1 < tmax && tid < 128) {
            int r = tid >> 1, p = tid & 1;
            int gcol = ((r >> 4) << 9) + hd0 + (r & 15);
            cp16(smu + (uint32_t)((ZXS_FLT + (((t + 1) & 1) << 9) + (r << 3) + (p << 2)) * 4),
                 g_Zx + ((size_t)((t + 1) << 11) + gcol) * 32 + (grp << 3) + (p << 2));
        }
        cp_commit();

        // ---- h-GEMM: 32 k-rows per warp, h LDG-direct from L2 (.cg) ----
        const float* hp = g_hT + (grp << 13) + ((t & 1) << 12)
                          + (krow0 << 3) + (bg << 2);
        const float* Wc = Wsm + (krow0 << 6) + (cw << 2);
        ull a0 = 0ull, a1 = 0ull, a2 = 0ull, a3 = 0ull;
        ull a4 = 0ull, a5 = 0ull, a6 = 0ull, a7 = 0ull;
        #pragma unroll 8
        for (int kk = 0; kk < 32; ++kk) {
            ull hx, hy;
            asm("ld.global.cg.v2.u64 {%0, %1}, [%2];"
                : "=l"(hx), "=l"(hy) : "l"(hp + (kk << 3)));
            float4 w = *(const float4*)(Wc + (kk << 6));
            ull w0 = splat2_(w.x), w1 = splat2_(w.y);
            ull w2 = splat2_(w.z), w3 = splat2_(w.w);
            a0 = ffma2_(hx, w0, a0);
            a1 = ffma2_(hy, w0, a1);
            a2 = ffma2_(hx, w1, a2);
            a3 = ffma2_(hy, w1, a3);
            a4 = ffma2_(hx, w2, a4);
            a5 = ffma2_(hy, w2, a5);
            a6 = ffma2_(hx, w3, a6);
            a7 = ffma2_(hy, w3, a7);
        }
        {   // partials: zred[ws][64 c][8 b]; per col 8 floats = 4 u64, lane owns bg half
            ull* zru = (ull*)zred;
            int cb = (wid << 6) + (cw << 2);
            zru[((cb    ) << 2) + (bg << 1)]     = a0;
            zru[((cb    ) << 2) + (bg << 1) + 1] = a1;
            zru[((cb + 1) << 2) + (bg << 1)]     = a2;
            zru[((cb + 1) << 2) + (bg << 1) + 1] = a3;
            zru[((cb + 2) << 2) + (bg << 1)]     = a4;
            zru[((cb + 2) << 2) + (bg << 1) + 1] = a5;
            zru[((cb + 3) << 2) + (bg << 1)]     = a6;
            zru[((cb + 3) << 2) + (bg << 1) + 1] = a7;
        }
        CP_WAIT(1);
        __syncthreads();

        // ---- gates + state update (128 threads: jj 0..15, b 0..7; state in regs) ----
        if (tid < 128) {
            const float* zx_t = zxs + ((t & 1) << 9);
            float gt[4];
            #pragma unroll
            for (int gate = 0; gate < 4; ++gate) {
                int c = (gate << 4) + gjj;
                float s = zx_t[(c << 3) + gbb];
                #pragma unroll
                for (int ks = 0; ks < 16; ++ks) s += zred[(((ks << 6) + c) << 3) + gbb];
                gt[gate] = s;
            }
            float i_ = fsig_(gt[0]);
            float jt = ftanh_(gt[1]);
            float f_ = fsig_(gt[2] + 1.f);
            float o_ = fsig_(gt[3]);
            float cnew = c_st * f_ + i_ * jt;
            float hnew = ftanh_(cnew) * o_;
            bool m = t < mylen;
            c_st = m ? cnew : c_st;
            float hout = m ? hnew : h_st;
            h_st = hout;
            int hd = hd0 + gjj;
            g_hT[(grp << 13) + (((t + 1) & 1) << 12) + (hd << 3) + gbb] = hout;
            g_Y[((size_t)(t << 9) + hd) * 32 + (grp << 3) + gbb] = m ? hnew : 0.f;
        }
        __syncthreads();

        // ---- group barrier: one arrive per block, single poller ----
        if (tid == 0) {
            asm volatile("red.release.gpu.global.add.u32 [%0], %1;"
                         :: "l"(barp), "r"(1u) : "memory");
            unsigned target = (unsigned)(t + 1) * GPB;
            unsigned v;
            do {
                asm volatile("ld.acquire.gpu.global.u32 %0, [%1];"
                             : "=r"(v) : "l"(barp) : "memory");
            } while (v < target);
        }
        __syncthreads();
    }
}

// ================================================================================
// Phase C: projection + masked xent. one block per t
// ================================================================================
#define LS_YS   0
#define LS_PW   16384
#define LS_LG   (16384 + 25600)
#define LOSS_SMEM ((LS_LG + 1600) * 4)

__global__ void __launch_bounds__(256, 1)
loss_kernel(const int* __restrict__ a, const int* __restrict__ lengths,
            const float* __restrict__ pW, const float* __restrict__ pb)
{
    extern __shared__ float lsm[];
    float* ys  = lsm + LS_YS;
    float* pWs = lsm + LS_PW;
    float* lg  = lsm + LS_LG;
    const int t = blockIdx.x;
    const int tid = threadIdx.x;

    {
        const float4* src = (const float4*)(g_Y + (size_t)t * (H_ * B_));
        float4* dst = (float4*)ys;
        #pragma unroll
        for (int i = 0; i < 16; ++i) dst[tid + i * 256] = src[tid + i * 256];
        const float4* ps = (const float4*)pW;
        float4* pd = (float4*)pWs;
        #pragma unroll
        for (int i = 0; i < 25; ++i) pd[tid + i * 256] = ps[tid + i * 256];
    }
    __syncthreads();

    {
        int b = tid & 31, l0 = tid >> 5;
        for (int l = l0; l < 50; l += 8) {
            float s = __ldg(&pb[l]);
            #pragma unroll 8
            for (int h = 0; h < 512; ++h) s += ys[h * 32 + b] * pWs[h * 50 + l];
            lg[l * 32 + b] = fmaxf(s, 0.f);
        }
    }
    __syncthreads();

    if (tid < 32) {
        int b = tid;
        if (t < __ldg(&lengths[b])) {
            float mx = lg[b];
            #pragma unroll
            for (int l = 1; l < 50; ++l) mx = fmaxf(mx, lg[l * 32 + b]);
            float se = 0.f;
            #pragma unroll
            for (int l = 0; l < 50; ++l) se += expf(lg[l * 32 + b] - mx);
            float lse = logf(se) + mx;
            int lab = __ldg(&a[(b << 9) + t]);
            atomicAdd(&g_acc[b], lse - lg[lab * 32 + b]);
        }
    }
}

__global__ void final_kernel(const int* __restrict__ lengths, float* __restrict__ out) {
    if (threadIdx.x == 0) {
        float s = 0.f;
        for (int b = 0; b < B_; ++b) s += g_acc[b] / (float)lengths[b];
        out[0] = s * (1.f / (float)B_);
    }
}

// ---------------- launch ----------------------------------------------------------
extern "C" void kernel_launch(void* const* d_in, const int* in_sizes, int n_in,
                              void* d_out, int out_size) {
    const int*   q       = (const int*)d_in[0];
    const int*   a       = (const int*)d_in[1];
    const int*   lengths = (const int*)d_in[2];
    const float* we      = (const float*)d_in[3];
    const float* W       = (const float*)d_in[4];
    const float* bvec    = (const float*)d_in[5];
    const float* pW      = (const float*)d_in[6];
    const float* pb      = (const float*)d_in[7];
    float* out = (float*)d_out;

    cudaFuncSetAttribute(zx_kernel, cudaFuncAttributeMaxDynamicSharedMemorySize, ZX_SMEM);
    cudaFuncSetAttribute(lstm_kernel, cudaFuncAttributeMaxDynamicSharedMemorySize, SMEM_TOTAL);
    cudaFuncSetAttribute(loss_kernel, cudaFuncAttributeMaxDynamicSharedMemorySize, LOSS_SMEM);

    zx_kernel<<<T_ * 4, 256, ZX_SMEM>>>(q, we, W, bvec, lengths);
    lstm_kernel<<<NBLK, NT, SMEM_TOTAL>>>(lengths, W);
    loss_kernel<<<T_, 256, LOSS_SMEM>>>(a, lengths, pW, pb);
    final_kernel<<<1, 32>>>(lengths, out);
}

// round 14
// speedup vs baseline: 1.3298x; 1.0099x over previous
#include <cuda_runtime.h>
#include <math.h>
#include <stdint.h>

#define B_   32
#define T_   512
#define E_   256
#define H_   512
#define L_   50
#define NT   512     // 16 warps
#define NBLK 128     // recurrent blocks, 1/SM
#define GPB  32      // blocks per batch-group (4 groups of 8 batches)

typedef unsigned long long ull;

// ---------------- device globals -----------------------------------------------
__device__ __align__(16) float g_hT[4 * 2 * H_ * 8];    // [grp][buf][hd][8b]
__device__ __align__(16) float g_Y[T_ * H_ * B_];       // [t][hd][32b] (zero-init .bss)
__device__ __align__(16) float g_Zx[(size_t)T_ * 2048 * B_]; // [t][col][32b]
__device__ float g_acc[B_];
__device__ unsigned g_barc[4 * 32];                     // per-group counters, 128B apart

// ---------------- helpers --------------------------------------------------------
__device__ __forceinline__ ull ffma2_(ull a, ull b, ull c) {
    ull d;
    asm("fma.rn.f32x2 %0, %1, %2, %3;" : "=l"(d) : "l"(a), "l"(b), "l"(c));
    return d;
}
__device__ __forceinline__ ull splat2_(float x) {
    ull r; unsigned xi = __float_as_uint(x);
    asm("mov.b64 %0, {%1, %1};" : "=l"(r) : "r"(xi));
    return r;
}
__device__ __forceinline__ void cp16(uint32_t dst, const void* src) {
    asm volatile("cp.async.cg.shared.global [%0], [%1], 16;" :: "r"(dst), "l"(src));
}
__device__ __forceinline__ void cp_commit() { asm volatile("cp.async.commit_group;"); }
#define CP_WAIT(N) asm volatile("cp.async.wait_group %0;" :: "n"(N) : "memory")

__device__ __forceinline__ float fsig_(float x) {
    x = fminf(fmaxf(x, -30.f), 30.f);
    float e = __expf(-x);
    return __fdividef(1.f, 1.f + e);
}
__device__ __forceinline__ float ftanh_(float x) {
    x = fminf(fmaxf(x, -15.f), 15.f);
    float e = __expf(-2.f * x);
    return __fdividef(1.f - e, 1.f + e);
}

// ================================================================================
// Phase A: zx precompute.  grid = (T_ * 4); block 0 also resets state.
// ================================================================================
#define ZXD_OFF  0
#define ZWB_OFF  (256*32)
#define ZX_SMEM  ((8192 + 3*8192) * 4)
#define XT_PAD   261

__global__ void __launch_bounds__(256, 1)
zx_kernel(const int* __restrict__ q, const float* __restrict__ we,
          const float* __restrict__ W, const float* __restrict__ bvec,
          const int* __restrict__ lengths)
{
    extern __shared__ float sm[];
    float* XD = sm + ZXD_OFF;
    float* WB = sm + ZWB_OFF;
    float* XT = sm + ZWB_OFF;
    const uint32_t smu = (uint32_t)__cvta_generic_to_shared(sm);
    __shared__ int qrow[32];
    __shared__ int smax[1];

    const int tid = threadIdx.x;
    const int t   = blockIdx.x >> 2;
    const int c0  = (blockIdx.x & 3) << 9;

    if (blockIdx.x == 0) {                  // graph-replay-safe reset
        if (tid < 128) g_barc[tid] = 0u;
        if (tid < 32)  g_acc[tid] = 0.f;
        float4 z4 = make_float4(0.f, 0.f, 0.f, 0.f);
        float4* hp4 = (float4*)g_hT;
        #pragma unroll
        for (int i = 0; i < 32; ++i) hp4[tid + (i << 8)] = z4;   // 32768 floats
    }

    if (tid < 32) {
        int v = lengths[tid];
        #pragma unroll
        for (int o = 16; o > 0; o >>= 1) v = max(v, __shfl_xor_sync(0xffffffffu, v, o));
        if (tid == 0) smax[0] = v;
        qrow[tid] = q[(tid << 9) + t];
    }
    __syncthreads();
    if (t >= smax[0]) return;               // never consumed (g_Y stays zero there)

    #pragma unroll
    for (int i = 0; i < 32; ++i) {
        int idx = tid + (i << 8);
        int b = idx >> 8, k = idx & 255;
        XT[b * XT_PAD + k] = we[(((size_t)qrow[b]) << 8) + k];
    }
    __syncthreads();
    float xbuf[32];
    #pragma unroll
    for (int i = 0; i < 32; ++i) {
        int idx = tid + (i << 8);
        int k = idx >> 5, b = idx & 31;
        xbuf[i] = XT[b * XT_PAD + k];
    }
    __syncthreads();
    #pragma unroll
    for (int i = 0; i < 32; ++i) {
        int idx = tid + (i << 8);
        int k = idx >> 5, b = idx & 31;
        XD[k * 32 + b] = xbuf[i];
    }
    __syncthreads();

    const int bq = tid & 3;
    const int cq = tid >> 2;

    #pragma unroll
    for (int pc = 0; pc < 2; ++pc) {
        #pragma unroll
        for (int i = 0; i < 8; ++i) {
            int u = tid + (i << 8);
            int kk = u >> 7, c16 = u & 127;
            cp16(smu + (uint32_t)((ZWB_OFF + pc * 8192 + kk * 512 + (c16 << 2)) * 4),
                 W + ((size_t)(pc * 16 + kk)) * 2048 + c0 + (c16 << 2));
        }
        cp_commit();
    }

    ull acc[4][8];
    #pragma unroll
    for (int i = 0; i < 4; ++i)
        #pragma unroll
        for (int j = 0; j < 8; ++j) acc[i][j] = 0ull;

    for (int kc = 0; kc < 16; ++kc) {
        if (kc < 15) { CP_WAIT(1); } else { CP_WAIT(0); }
        __syncthreads();
        const float* Wc = WB + (kc % 3) * 8192;
        const float* Xc = XD + kc * 16 * 32;
        #pragma unroll
        for (int kk = 0; kk < 16; ++kk) {
            ulonglong2 xa = *(const ulonglong2*)(Xc + kk * 32 + bq * 8);
            ulonglong2 xb = *(const ulonglong2*)(Xc + kk * 32 + bq * 8 + 4);
            float4 w0 = *(const float4*)(Wc + kk * 512 + cq * 8);
            float4 w1 = *(const float4*)(Wc + kk * 512 + cq * 8 + 4);
            ull ws[8];
            ws[0] = splat2_(w0.x); ws[1] = splat2_(w0.y);
            ws[2] = splat2_(w0.z); ws[3] = splat2_(w0.w);
            ws[4] = splat2_(w1.x); ws[5] = splat2_(w1.y);
            ws[6] = splat2_(w1.z); ws[7] = splat2_(w1.w);
            #pragma unroll
            for (int c = 0; c < 8; ++c) {
                acc[0][c] = ffma2_(xa.x, ws[c], acc[0][c]);
                acc[1][c] = ffma2_(xa.y, ws[c], acc[1][c]);
                acc[2][c] = ffma2_(xb.x, ws[c], acc[2][c]);
                acc[3][c] = ffma2_(xb.y, ws[c], acc[3][c]);
            }
        }
        if (kc + 2 < 16) {
            int buf = (kc + 2) % 3;
            #pragma unroll
            for (int i = 0; i < 8; ++i) {
                int u = tid + (i << 8);
                int kk = u >> 7, c16 = u & 127;
                cp16(smu + (uint32_t)((ZWB_OFF + buf * 8192 + kk * 512 + (c16 << 2)) * 4),
                     W + ((size_t)((kc + 2) * 16 + kk)) * 2048 + c0 + (c16 << 2));
            }
            cp_commit();
        }
    }

    #pragma unroll
    for (int c = 0; c < 8; ++c) {
        int cg = c0 + cq * 8 + c;
        float bb = __ldg(&bvec[cg]);
        float* outp = g_Zx + ((size_t)t * 2048 + cg) * 32 + bq * 8;
        #pragma unroll
        for (int bp = 0; bp < 4; ++bp) {
            union { ull u; float2 f; } v; v.u = acc[bp][c];
            v.f.x += bb; v.f.y += bb;
            *(float2*)(outp + bp * 2) = v.f;
        }
    }
}

// ================================================================================
// Phase B: recurrence. 4 groups x 32 blocks; block = 16 hd x 64 cols x 8 batches.
// Two-phase gates: 512-thread z-reduction, then 128-thread nonlinearity.
// ================================================================================
#define WD_FLT   0                        // [512 k][64 c] floats = 32768
#define ZXS_FLT  32768                    // 2 x [64 c][8 b] = 1024
#define ZR_FLT   (ZXS_FLT + 1024)         // 33792 : [16 ws][64 c][8 b] = 8192
#define LEN_FLT  (ZR_FLT + 8192)          // 41984 : [8] ints
#define ZF_FLT   (LEN_FLT + 8)            // 41992 : [64 c][8 b] = 512
#define SMEM_TOTAL ((ZF_FLT + 512) * 4)   // 170016 B

__global__ void __launch_bounds__(NT, 1)
lstm_kernel(const int* __restrict__ lengths, const float* __restrict__ W)
{
    extern __shared__ float sm[];
    float* Wsm  = sm + WD_FLT;
    float* zxs  = sm + ZXS_FLT;
    float* zred = sm + ZR_FLT;
    int*   ls   = (int*)(sm + LEN_FLT);
    float* zfin = sm + ZF_FLT;
    const uint32_t smu = (uint32_t)__cvta_generic_to_shared(sm);

    const int tid = threadIdx.x;
    const int bid = blockIdx.x;
    const int grp = bid >> 5;              // 4 groups
    const int gb  = bid & 31;
    const int hd0 = gb << 4;               // 16 h-dims per block

    // prologue: W slice (rows 256..767, block's 64 cols), layout [k][64c]
    for (int i = tid; i < 512 * 64; i += NT) {
        int k = i >> 6, c = i & 63;        // c = gate*16 + jj
        Wsm[i] = W[((size_t)(256 + k)) * 2048 + (((c >> 4) << 9) + hd0 + (c & 15))];
    }
    if (tid < 8) ls[tid] = lengths[(grp << 3) + tid];
    __syncthreads();

    int tmax = ls[0];
    #pragma unroll
    for (int i = 1; i < 8; ++i) tmax = max(tmax, ls[i]);

    // zx(0) prefetch into buf 0: 64 cols x 8 floats = 128 cp16
    if (tid < 128) {
        int r = tid >> 1, p = tid & 1;     // col r, 16B half p
        int gcol = ((r >> 4) << 9) + hd0 + (r & 15);
        cp16(smu + (uint32_t)((ZXS_FLT + (r << 3) + (p << 2)) * 4),
             g_Zx + (size_t)gcol * 32 + (grp << 3) + (p << 2));
    }
    cp_commit();

    const int wid  = tid >> 5, lane = tid & 31;
    const int bg   = lane & 1;             // batch quad: b = 4bg..4bg+3
    const int cw   = lane >> 1;            // col quad:  c = 4cw..4cw+3
    const int krow0 = wid << 5;            // 32 k-rows per warp

    // persistent gate-thread state (tid < 128): b = tid&7, jj = tid>>3 (0..15)
    const int gbb = tid & 7, gjj = (tid >> 3) & 15;
    const int mylen = ls[gbb];
    float c_st = 0.f, h_st = 0.f;

    // phase-1 reduce decode (all 512 threads): c = tid>>3, b = tid&7
    const int rc = tid >> 3, rb = tid & 7;

    unsigned* barp = &g_barc[grp << 5];

    for (int t = 0; t < tmax; ++t) {
        // ---- issue zx(t+1) into the other buffer ----
        if (t + 1 < tmax && tid < 128) {
            int r = tid >> 1, p = tid & 1;
            int gcol = ((r >> 4) << 9) + hd0 + (r & 15);
            cp16(smu + (uint32_t)((ZXS_FLT + (((t + 1) & 1) << 9) + (r << 3) + (p << 2)) * 4),
                 g_Zx + ((size_t)((t + 1) << 11) + gcol) * 32 + (grp << 3) + (p << 2));
        }
        cp_commit();

        // ---- h-GEMM: 32 k-rows per warp, h LDG-direct from L2 (.cg) ----
        const float* hp = g_hT + (grp << 13) + ((t & 1) << 12)
                          + (krow0 << 3) + (bg << 2);
        const float* Wc = Wsm + (krow0 << 6) + (cw << 2);
        ull a0 = 0ull, a1 = 0ull, a2 = 0ull, a3 = 0ull;
        ull a4 = 0ull, a5 = 0ull, a6 = 0ull, a7 = 0ull;
        #pragma unroll 8
        for (int kk = 0; kk < 32; ++kk) {
            ull hx, hy;
            asm("ld.global.cg.v2.u64 {%0, %1}, [%2];"
                : "=l"(hx), "=l"(hy) : "l"(hp + (kk << 3)));
            float4 w = *(const float4*)(Wc + (kk << 6));
            ull w0 = splat2_(w.x), w1 = splat2_(w.y);
            ull w2 = splat2_(w.z), w3 = splat2_(w.w);
            a0 = ffma2_(hx, w0, a0);
            a1 = ffma2_(hy, w0, a1);
            a2 = ffma2_(hx, w1, a2);
            a3 = ffma2_(hy, w1, a3);
            a4 = ffma2_(hx, w2, a4);
            a5 = ffma2_(hy, w2, a5);
            a6 = ffma2_(hx, w3, a6);
            a7 = ffma2_(hy, w3, a7);
        }
        {   // partials: zred[ws][64 c][8 b]
            ull* zru = (ull*)zred;
            int cb = (wid << 6) + (cw << 2);
            zru[((cb    ) << 2) + (bg << 1)]     = a0;
            zru[((cb    ) << 2) + (bg << 1) + 1] = a1;
            zru[((cb + 1) << 2) + (bg << 1)]     = a2;
            zru[((cb + 1) << 2) + (bg << 1) + 1] = a3;
            zru[((cb + 2) << 2) + (bg << 1)]     = a4;
            zru[((cb + 2) << 2) + (bg << 1) + 1] = a5;
            zru[((cb + 3) << 2) + (bg << 1)]     = a6;
            zru[((cb + 3) << 2) + (bg << 1) + 1] = a7;
        }
        CP_WAIT(1);
        __syncthreads();

        // ---- phase 1: 512-thread z reduction (incl. zx) ----
        {
            const float* zx_t = zxs + ((t & 1) << 9);
            float s0 = zx_t[(rc << 3) + rb], s1 = 0.f;
            #pragma unroll
            for (int ks = 0; ks < 16; ks += 2) {
                s0 += zred[(((ks << 6) + rc) << 3) + rb];
                s1 += zred[((((ks + 1) << 6) + rc) << 3) + rb];
            }
            zfin[(rc << 3) + rb] = s0 + s1;
        }
        __syncthreads();

        // ---- phase 2: gates + state update (128 threads; state in regs) ----
        if (tid < 128) {
            float gt[4];
            #pragma unroll
            for (int gate = 0; gate < 4; ++gate)
                gt[gate] = zfin[(((gate << 4) + gjj) << 3) + gbb];
            float i_ = fsig_(gt[0]);
            float jt = ftanh_(gt[1]);
            float f_ = fsig_(gt[2] + 1.f);
            float o_ = fsig_(gt[3]);
            float cnew = c_st * f_ + i_ * jt;
            float hnew = ftanh_(cnew) * o_;
            bool m = t < mylen;
            c_st = m ? cnew : c_st;
            float hout = m ? hnew : h_st;
            h_st = hout;
            int hd = hd0 + gjj;
            g_hT[(grp << 13) + (((t + 1) & 1) << 12) + (hd << 3) + gbb] = hout;
            g_Y[((size_t)(t << 9) + hd) * 32 + (grp << 3) + gbb] = m ? hnew : 0.f;
        }
        __syncthreads();

        // ---- group barrier: one arrive per block, single poller ----
        if (tid == 0) {
            asm volatile("red.release.gpu.global.add.u32 [%0], %1;"
                         :: "l"(barp), "r"(1u) : "memory");
            unsigned target = (unsigned)(t + 1) * GPB;
            unsigned v;
            do {
                asm volatile("ld.acquire.gpu.global.u32 %0, [%1];"
                             : "=r"(v) : "l"(barp) : "memory");
            } while (v < target);
        }
        __syncthreads();
    }
}

// ================================================================================
// Phase C: projection + masked xent. one block per t; register-blocked FFMA2.
// thread = (bq = tid&3 -> 8 batches, l = tid>>2, active l<50)
// ================================================================================
#define LS_YS   0
#define LS_PW   16384
#define LS_LG   (16384 + 25600)
#define LOSS_SMEM ((LS_LG + 1600) * 4)

__global__ void __launch_bounds__(256, 1)
loss_kernel(const int* __restrict__ a, const int* __restrict__ lengths,
            const float* __restrict__ pW, const float* __restrict__ pb)
{
    extern __shared__ float lsm[];
    float* ys  = lsm + LS_YS;
    float* pWs = lsm + LS_PW;
    float* lg  = lsm + LS_LG;
    const int t = blockIdx.x;
    const int tid = threadIdx.x;

    {
        const float4* src = (const float4*)(g_Y + (size_t)t * (H_ * B_));
        float4* dst = (float4*)ys;
        #pragma unroll
        for (int i = 0; i < 16; ++i) dst[tid + i * 256] = src[tid + i * 256];
        const float4* ps = (const float4*)pW;
        float4* pd = (float4*)pWs;
        #pragma unroll
        for (int i = 0; i < 25; ++i) pd[tid + i * 256] = ps[tid + i * 256];
    }
    __syncthreads();

    {
        const int bq = tid & 3;            // 8 batches: 8bq..8bq+7
        const int l  = tid >> 2;           // logit column
        if (l < 50) {
            ull ac0 = 0ull, ac1 = 0ull, ac2 = 0ull, ac3 = 0ull;
            #pragma unroll 4
            for (int h = 0; h < 512; ++h) {
                const ull* yp = (const ull*)(ys + (h << 5) + (bq << 3));
                ull wv = splat2_(pWs[h * 50 + l]);
                ac0 = ffma2_(yp[0], wv, ac0);
                ac1 = ffma2_(yp[1], wv, ac1);
                ac2 = ffma2_(yp[2], wv, ac2);
                ac3 = ffma2_(yp[3], wv, ac3);
            }
            float bb = __ldg(&pb[l]);
            union { ull u; float2 f; } v;
            ull accs[4] = {ac0, ac1, ac2, ac3};
            #pragma unroll
            for (int j = 0; j < 4; ++j) {
                v.u = accs[j];
                lg[l * 32 + (bq << 3) + 2 * j]     = fmaxf(v.f.x + bb, 0.f);
                lg[l * 32 + (bq << 3) + 2 * j + 1] = fmaxf(v.f.y + bb, 0.f);
            }
        }
    }
    __syncthreads();

    if (tid < 32) {
        int b = tid;
        if (t < __ldg(&lengths[b])) {
            float mx = lg[b];
            #pragma unroll
            for (int l = 1; l < 50; ++l) mx = fmaxf(mx, lg[l * 32 + b]);
            float se = 0.f;
            #pragma unroll
            for (int l = 0; l < 50; ++l) se += expf(lg[l * 32 + b] - mx);
            float lse = logf(se) + mx;
            int lab = __ldg(&a[(b << 9) + t]);
            atomicAdd(&g_acc[b], lse - lg[lab * 32 + b]);
        }
    }
}

__global__ void final_kernel(const int* __restrict__ lengths, float* __restrict__ out) {
    if (threadIdx.x == 0) {
        float s = 0.f;
        for (int b = 0; b < B_; ++b) s += g_acc[b] / (float)lengths[b];
        out[0] = s * (1.f / (float)B_);
    }
}

// ---------------- launch ----------------------------------------------------------
extern "C" void kernel_launch(void* const* d_in, const int* in_sizes, int n_in,
                              void* d_out, int out_size) {
    const int*   q       = (const int*)d_in[0];
    const int*   a       = (const int*)d_in[1];
    const int*   lengths = (const int*)d_in[2];
    const float* we      = (const float*)d_in[3];
    const float* W       = (const float*)d_in[4];
    const float* bvec    = (const float*)d_in[5];
    const float* pW      = (const float*)d_in[6];
    const float* pb      = (const float*)d_in[7];
    float* out = (float*)d_out;

    cudaFuncSetAttribute(zx_kernel, cudaFuncAttributeMaxDynamicSharedMemorySize, ZX_SMEM);
    cudaFuncSetAttribute(lstm_kernel, cudaFuncAttributeMaxDynamicSharedMemorySize, SMEM_TOTAL);
    cudaFuncSetAttribute(loss_kernel, cudaFuncAttributeMaxDynamicSharedMemorySize, LOSS_SMEM);

    zx_kernel<<<T_ * 4, 256, ZX_SMEM>>>(q, we, W, bvec, lengths);
    lstm_kernel<<<NBLK, NT, SMEM_TOTAL>>>(lengths, W);
    loss_kernel<<<T_, 256, LOSS_SMEM>>>(a, lengths, pW, pb);
    final_kernel<<<1, 32>>>(lengths, out);
}